// round 3
// baseline (speedup 1.0000x reference)
#include <cuda_runtime.h>
#include <cstddef>

#define NN 50000
#define EE 800000
#define FD 128
#define SCAN_B 512
#define SCAN_NB 98   // ceil(50000/512)

// ---------------- scratch (static device globals; no runtime alloc) ----------------
__device__ int   g_is64;                // 1 if edge_index is int64, 0 if int32
__device__ float g_dinv[NN];            // deg -> rsqrt(deg)
__device__ int   g_cnt[NN];             // histogram, then write-cursor
__device__ int   g_rowptr[NN + 1];
__device__ int   g_blocksum[SCAN_NB];
__device__ int   g_blockoff[SCAN_NB];
__device__ int   g_csr_src[EE];
__device__ float g_csr_nrm[EE];
__device__ float g_hA[(size_t)NN * FD];
__device__ float g_hB[(size_t)NN * FD];

// ---------------- edge_index dtype detection ----------------
// If data is int64 (values < 2^31), every odd 32-bit word (high half) is 0.
// If data is int32, odd words are random node ids; all-zero is impossible in practice.
__global__ void detect_kernel(const unsigned int* __restrict__ w) {
    unsigned int v = w[2 * threadIdx.x + 1];
    unsigned int all0 = __ballot_sync(0xffffffffu, v == 0u);
    if (threadIdx.x == 0) g_is64 = (all0 == 0xffffffffu) ? 1 : 0;
}

__device__ __forceinline__ int edge_at(const void* ei, long long pos) {
    if (g_is64) return (int)((const long long*)ei)[pos];
    return ((const int*)ei)[pos];
}

// ---------------- gcn_norm prep ----------------
__global__ void init_kernel() {
    int i = blockIdx.x * blockDim.x + threadIdx.x;
    if (i < NN) { g_dinv[i] = 1.0f; g_cnt[i] = 0; }   // deg starts at 1 (self loop)
}

__global__ void deg_kernel(const void* __restrict__ ei, const float* __restrict__ ew) {
    int e = blockIdx.x * blockDim.x + threadIdx.x;
    if (e < EE) {
        int d = edge_at(ei, (long long)EE + e);
        atomicAdd(&g_dinv[d], ew[e]);
        atomicAdd(&g_cnt[d], 1);
    }
}

__global__ void rsqrt_kernel() {
    int i = blockIdx.x * blockDim.x + threadIdx.x;
    if (i < NN) g_dinv[i] = rsqrtf(g_dinv[i]);   // deg >= 1 always
}

// ---------------- exclusive scan of g_cnt -> g_rowptr ----------------
__global__ void scan1_kernel() {
    __shared__ int s[SCAN_B];
    int t = threadIdx.x;
    int i = blockIdx.x * SCAN_B + t;
    int v = (i < NN) ? g_cnt[i] : 0;
    s[t] = v;
    __syncthreads();
    for (int off = 1; off < SCAN_B; off <<= 1) {
        int tmp = (t >= off) ? s[t - off] : 0;
        __syncthreads();
        s[t] += tmp;
        __syncthreads();
    }
    if (i < NN) g_rowptr[i] = s[t] - v;          // exclusive, local to block
    if (t == SCAN_B - 1) g_blocksum[blockIdx.x] = s[t];
}

__global__ void scan2_kernel() {
    __shared__ int s[128];
    int t = threadIdx.x;
    int v = (t < SCAN_NB) ? g_blocksum[t] : 0;
    s[t] = v;
    __syncthreads();
    for (int off = 1; off < 128; off <<= 1) {
        int tmp = (t >= off) ? s[t - off] : 0;
        __syncthreads();
        s[t] += tmp;
        __syncthreads();
    }
    if (t < SCAN_NB) g_blockoff[t] = s[t] - v;   // exclusive
}

__global__ void scan3_kernel() {
    int i = blockIdx.x * blockDim.x + threadIdx.x;
    if (i < NN) {
        int v = g_rowptr[i] + g_blockoff[i / SCAN_B];
        g_rowptr[i] = v;
        g_cnt[i] = v;                            // reuse as write cursor
    }
    if (i == 0) g_rowptr[NN] = EE;
}

// ---------------- CSR build (edges bucketed by dst) ----------------
__global__ void csr_kernel(const void* __restrict__ ei, const float* __restrict__ ew) {
    int e = blockIdx.x * blockDim.x + threadIdx.x;
    if (e < EE) {
        int s = edge_at(ei, e);
        int d = edge_at(ei, (long long)EE + e);
        float nrm = g_dinv[s] * ew[e] * g_dinv[d];
        int pos = atomicAdd(&g_cnt[d], 1);
        g_csr_src[pos] = s;
        g_csr_nrm[pos] = nrm;
    }
}

// ---------------- GEMM: Y[n,128] = X[n,128] @ W[128,128] (+bias) ----------------
#define GM 64
__global__ void gemm_kernel(const float* __restrict__ X, const float* __restrict__ W,
                            const float* __restrict__ bias, float* __restrict__ Y, int n) {
    __shared__ float sW[16][128];
    __shared__ float sX[64][16];
    int tid = threadIdx.x;            // 256
    int ty = tid >> 4;                // 0..15 (row group)
    int tx = tid & 15;                // 0..15 (col group)
    int row0 = blockIdx.x * GM;

    float acc[4][8];
    #pragma unroll
    for (int r = 0; r < 4; r++)
        #pragma unroll
        for (int c = 0; c < 8; c++) acc[r][c] = 0.f;

    for (int kt = 0; kt < 8; kt++) {
        // stage W tile 16x128
        #pragma unroll
        for (int j = 0; j < 2; j++) {
            int i = tid + 256 * j;                // 0..511 float4s
            int r = i >> 5, c = (i & 31) << 2;
            *(float4*)&sW[r][c] = *(const float4*)&W[(kt * 16 + r) * 128 + c];
        }
        // stage X tile 64x16
        {
            int r = tid >> 2, c = (tid & 3) << 2;
            float4 v = make_float4(0.f, 0.f, 0.f, 0.f);
            if (row0 + r < n)
                v = *(const float4*)&X[(size_t)(row0 + r) * 128 + kt * 16 + c];
            *(float4*)&sX[r][c] = v;
        }
        __syncthreads();
        #pragma unroll
        for (int kk = 0; kk < 16; kk++) {
            float wv[8];
            *(float4*)&wv[0] = *(float4*)&sW[kk][tx * 8];
            *(float4*)&wv[4] = *(float4*)&sW[kk][tx * 8 + 4];
            #pragma unroll
            for (int r = 0; r < 4; r++) {
                float xv = sX[ty + 16 * r][kk];
                #pragma unroll
                for (int c = 0; c < 8; c++) acc[r][c] = fmaf(xv, wv[c], acc[r][c]);
            }
        }
        __syncthreads();
    }
    float bv[8];
    #pragma unroll
    for (int c = 0; c < 8; c++) bv[c] = bias ? bias[tx * 8 + c] : 0.f;
    #pragma unroll
    for (int r = 0; r < 4; r++) {
        int row = row0 + ty + 16 * r;
        if (row < n) {
            float4 o0 = make_float4(acc[r][0] + bv[0], acc[r][1] + bv[1],
                                    acc[r][2] + bv[2], acc[r][3] + bv[3]);
            float4 o1 = make_float4(acc[r][4] + bv[4], acc[r][5] + bv[5],
                                    acc[r][6] + bv[6], acc[r][7] + bv[7]);
            *(float4*)&Y[(size_t)row * 128 + tx * 8] = o0;
            *(float4*)&Y[(size_t)row * 128 + tx * 8 + 4] = o1;
        }
    }
}

// ---------------- aggregate: Y[i] = relu(sum_e nrm*H[src] + dinv_i^2*H[i] + b) ----------------
__global__ void aggregate_kernel(const float* __restrict__ H, const float* __restrict__ bias,
                                 float* __restrict__ Y) {
    int warp = (blockIdx.x * blockDim.x + threadIdx.x) >> 5;
    int lane = threadIdx.x & 31;
    if (warp >= NN) return;
    int beg = g_rowptr[warp];
    int end = g_rowptr[warp + 1];
    const float4* __restrict__ H4 = (const float4*)H;

    float4 acc = make_float4(0.f, 0.f, 0.f, 0.f);
    int e = beg;
    for (; e + 4 <= end; e += 4) {
        int   s0 = g_csr_src[e + 0], s1 = g_csr_src[e + 1];
        int   s2 = g_csr_src[e + 2], s3 = g_csr_src[e + 3];
        float n0 = g_csr_nrm[e + 0], n1 = g_csr_nrm[e + 1];
        float n2 = g_csr_nrm[e + 2], n3 = g_csr_nrm[e + 3];
        float4 h0 = __ldg(H4 + (size_t)s0 * 32 + lane);
        float4 h1 = __ldg(H4 + (size_t)s1 * 32 + lane);
        float4 h2 = __ldg(H4 + (size_t)s2 * 32 + lane);
        float4 h3 = __ldg(H4 + (size_t)s3 * 32 + lane);
        acc.x = fmaf(n0, h0.x, acc.x); acc.y = fmaf(n0, h0.y, acc.y);
        acc.z = fmaf(n0, h0.z, acc.z); acc.w = fmaf(n0, h0.w, acc.w);
        acc.x = fmaf(n1, h1.x, acc.x); acc.y = fmaf(n1, h1.y, acc.y);
        acc.z = fmaf(n1, h1.z, acc.z); acc.w = fmaf(n1, h1.w, acc.w);
        acc.x = fmaf(n2, h2.x, acc.x); acc.y = fmaf(n2, h2.y, acc.y);
        acc.z = fmaf(n2, h2.z, acc.z); acc.w = fmaf(n2, h2.w, acc.w);
        acc.x = fmaf(n3, h3.x, acc.x); acc.y = fmaf(n3, h3.y, acc.y);
        acc.z = fmaf(n3, h3.z, acc.z); acc.w = fmaf(n3, h3.w, acc.w);
    }
    for (; e < end; e++) {
        int s = g_csr_src[e];
        float nv = g_csr_nrm[e];
        float4 h = __ldg(H4 + (size_t)s * 32 + lane);
        acc.x = fmaf(nv, h.x, acc.x); acc.y = fmaf(nv, h.y, acc.y);
        acc.z = fmaf(nv, h.z, acc.z); acc.w = fmaf(nv, h.w, acc.w);
    }
    // self loop: norm = dinv^2 * 1
    float di = g_dinv[warp];
    float sn = di * di;
    float4 hs = __ldg(H4 + (size_t)warp * 32 + lane);
    acc.x = fmaf(sn, hs.x, acc.x); acc.y = fmaf(sn, hs.y, acc.y);
    acc.z = fmaf(sn, hs.z, acc.z); acc.w = fmaf(sn, hs.w, acc.w);

    float4 b = __ldg((const float4*)bias + lane);
    acc.x = fmaxf(acc.x + b.x, 0.f);
    acc.y = fmaxf(acc.y + b.y, 0.f);
    acc.z = fmaxf(acc.z + b.z, 0.f);
    acc.w = fmaxf(acc.w + b.w, 0.f);
    ((float4*)Y)[(size_t)warp * 32 + lane] = acc;
}

// ---------------- launch ----------------
extern "C" void kernel_launch(void* const* d_in, const int* in_sizes, int n_in,
                              void* d_out, int out_size) {
    // Identify inputs by element count (robust to metadata ordering).
    const float* x = nullptr;
    const float* ew = nullptr;
    const void*  ei = nullptr;
    const float* Ws[3] = {nullptr, nullptr, nullptr};   // W1, W2, Wfc in order
    const float* bs[3] = {nullptr, nullptr, nullptr};   // b1, b2, bfc in order
    int nW = 0, nb = 0;
    for (int i = 0; i < n_in; i++) {
        long long sz = in_sizes[i];
        if      (sz == (long long)NN * FD)  x  = (const float*)d_in[i];
        else if (sz == EE)                  ew = (const float*)d_in[i];
        else if (sz == 2LL * EE)            ei = d_in[i];
        else if (sz == FD * FD) { if (nW < 3) Ws[nW++] = (const float*)d_in[i]; }
        else if (sz == FD)      { if (nb < 3) bs[nb++] = (const float*)d_in[i]; }
    }
    const float *W1 = Ws[0], *W2 = Ws[1], *Wfc = Ws[2];
    const float *b1 = bs[0], *b2 = bs[1], *bfc = bs[2];
    float* out = (float*)d_out;

    float* hA; cudaGetSymbolAddress((void**)&hA, g_hA);
    float* hB; cudaGetSymbolAddress((void**)&hB, g_hB);

    int nodeBlocks = (NN + 255) / 256;
    int edgeBlocks = (EE + 255) / 256;
    int gemmBlocks = (NN + GM - 1) / GM;
    int aggBlocks  = (NN + 7) / 8;      // 8 warps/block

    // dtype detect + norm + CSR build
    detect_kernel<<<1, 32>>>((const unsigned int*)ei);
    init_kernel<<<nodeBlocks, 256>>>();
    deg_kernel<<<edgeBlocks, 256>>>(ei, ew);
    rsqrt_kernel<<<nodeBlocks, 256>>>();
    scan1_kernel<<<SCAN_NB, SCAN_B>>>();
    scan2_kernel<<<1, 128>>>();
    scan3_kernel<<<nodeBlocks, 256>>>();
    csr_kernel<<<edgeBlocks, 256>>>(ei, ew);

    // layer 1
    gemm_kernel<<<gemmBlocks, 256>>>(x, W1, nullptr, hA, NN);
    aggregate_kernel<<<aggBlocks, 256>>>(hA, b1, hB);
    // layer 2
    gemm_kernel<<<gemmBlocks, 256>>>(hB, W2, nullptr, hA, NN);
    aggregate_kernel<<<aggBlocks, 256>>>(hA, b2, hB);
    // final FC
    gemm_kernel<<<gemmBlocks, 256>>>(hB, Wfc, bfc, out, NN);
}

// round 4
// speedup vs baseline: 1.2116x; 1.2116x over previous
#include <cuda_runtime.h>
#include <cstddef>

#define NN 50000
#define EE 800000
#define FD 128
#define SCAN_B 512
#define SCAN_NB 98   // ceil(50000/512)

// ---------------- scratch (static device globals; no runtime alloc) ----------------
__device__ int   g_is64;                // 1 if edge_index is int64, 0 if int32
__device__ float g_dinv[NN];            // deg -> rsqrt(deg)
__device__ int   g_cnt[NN];             // histogram, then write-cursor
__device__ int   g_rowptr[NN + 1];
__device__ int   g_blocksum[SCAN_NB];
__device__ int   g_blockoff[SCAN_NB];
__device__ int   g_csr_src[EE];
__device__ float g_csr_nrm[EE];
__device__ float g_hA[(size_t)NN * FD];
__device__ float g_hB[(size_t)NN * FD];

// ---------------- dtype helpers ----------------
__device__ __forceinline__ int edge_at(const void* ei, long long pos) {
    if (g_is64) return (int)((const long long*)ei)[pos];
    return ((const int*)ei)[pos];
}

// ---------------- init (+dtype detect in block 0) ----------------
// int64 edge values < 2^31 => every odd 32-bit word is 0. int32 data: odd words
// are random node ids; P(first 32 odd words all zero) is negligible.
__global__ void init_kernel(const unsigned int* __restrict__ w) {
    int i = blockIdx.x * blockDim.x + threadIdx.x;
    if (blockIdx.x == 0 && threadIdx.x < 32) {
        unsigned int v = w[2 * threadIdx.x + 1];
        unsigned int all0 = __ballot_sync(0xffffffffu, v == 0u);
        if (threadIdx.x == 0) g_is64 = (all0 == 0xffffffffu) ? 1 : 0;
    }
    if (i < NN) { g_dinv[i] = 1.0f; g_cnt[i] = 0; }   // deg starts at 1 (self loop)
}

__global__ void deg_kernel(const void* __restrict__ ei, const float* __restrict__ ew) {
    int e = blockIdx.x * blockDim.x + threadIdx.x;
    if (e < EE) {
        int d = edge_at(ei, (long long)EE + e);
        atomicAdd(&g_dinv[d], ew[e]);
        atomicAdd(&g_cnt[d], 1);
    }
}

// ---------------- exclusive scan of g_cnt -> g_rowptr ----------------
__global__ void scan1_kernel() {
    __shared__ int s[SCAN_B];
    int t = threadIdx.x;
    int i = blockIdx.x * SCAN_B + t;
    int v = (i < NN) ? g_cnt[i] : 0;
    s[t] = v;
    __syncthreads();
    for (int off = 1; off < SCAN_B; off <<= 1) {
        int tmp = (t >= off) ? s[t - off] : 0;
        __syncthreads();
        s[t] += tmp;
        __syncthreads();
    }
    if (i < NN) g_rowptr[i] = s[t] - v;          // exclusive, local to block
    if (t == SCAN_B - 1) g_blocksum[blockIdx.x] = s[t];
}

__global__ void scan2_kernel() {
    __shared__ int s[128];
    int t = threadIdx.x;
    int v = (t < SCAN_NB) ? g_blocksum[t] : 0;
    s[t] = v;
    __syncthreads();
    for (int off = 1; off < 128; off <<= 1) {
        int tmp = (t >= off) ? s[t - off] : 0;
        __syncthreads();
        s[t] += tmp;
        __syncthreads();
    }
    if (t < SCAN_NB) g_blockoff[t] = s[t] - v;   // exclusive
}

// scan3 also performs the deg -> rsqrt(deg) conversion (deg complete by now)
__global__ void scan3_kernel() {
    int i = blockIdx.x * blockDim.x + threadIdx.x;
    if (i < NN) {
        int v = g_rowptr[i] + g_blockoff[i / SCAN_B];
        g_rowptr[i] = v;
        g_cnt[i] = v;                            // reuse as write cursor
        g_dinv[i] = rsqrtf(g_dinv[i]);           // deg >= 1 always
    }
    if (i == 0) g_rowptr[NN] = EE;
}

// ---------------- CSR build (edges bucketed by dst) ----------------
__global__ void csr_kernel(const void* __restrict__ ei, const float* __restrict__ ew) {
    int e = blockIdx.x * blockDim.x + threadIdx.x;
    if (e < EE) {
        int s = edge_at(ei, e);
        int d = edge_at(ei, (long long)EE + e);
        float nrm = g_dinv[s] * ew[e] * g_dinv[d];
        int pos = atomicAdd(&g_cnt[d], 1);
        g_csr_src[pos] = s;
        g_csr_nrm[pos] = nrm;
    }
}

// ---------------- GEMM: Y[n,128] = X[n,128] @ W[128,128] (+bias) ----------------
// 128x128 tile, 256 threads, 8x8 micro-tile, packed fma.rn.f32x2 accumulators.
#define BM 128
__global__ __launch_bounds__(256) void gemm_kernel(const float* __restrict__ X,
                                                   const float* __restrict__ W,
                                                   const float* __restrict__ bias,
                                                   float* __restrict__ Y, int n) {
    __shared__ float sX[BM][16];
    __shared__ float sW[16][128];
    int tid = threadIdx.x;
    int tx = tid & 15;                // col group: cols tx*8 .. tx*8+7
    int ty = tid >> 4;                // row group: rows ty*8 .. ty*8+7
    int row0 = blockIdx.x * BM;

    unsigned long long acc[8][4];     // 8 rows x 4 packed col-pairs
    #pragma unroll
    for (int i = 0; i < 8; i++)
        #pragma unroll
        for (int p = 0; p < 4; p++) acc[i][p] = 0ull;

    for (int kt = 0; kt < 8; kt++) {
        // stage W tile 16x128 (512 float4, 2 per thread)
        #pragma unroll
        for (int j = 0; j < 2; j++) {
            int i4 = tid + 256 * j;
            int r = i4 >> 5, c = (i4 & 31) << 2;
            *(float4*)&sW[r][c] = *(const float4*)&W[(kt * 16 + r) * 128 + c];
        }
        // stage X tile 128x16 (512 float4, 2 per thread)
        #pragma unroll
        for (int j = 0; j < 2; j++) {
            int i4 = tid + 256 * j;
            int r = i4 >> 2, c = (i4 & 3) << 2;
            float4 v = make_float4(0.f, 0.f, 0.f, 0.f);
            if (row0 + r < n)
                v = *(const float4*)&X[(size_t)(row0 + r) * 128 + kt * 16 + c];
            *(float4*)&sX[r][c] = v;
        }
        __syncthreads();
        #pragma unroll
        for (int kk = 0; kk < 16; kk++) {
            ulonglong2 wa = *(ulonglong2*)&sW[kk][tx * 8];
            ulonglong2 wb = *(ulonglong2*)&sW[kk][tx * 8 + 4];
            #pragma unroll
            for (int i = 0; i < 8; i++) {
                float xv = sX[ty * 8 + i][kk];
                unsigned long long xp;
                asm("mov.b64 %0, {%1, %1};" : "=l"(xp) : "f"(xv));
                asm("fma.rn.f32x2 %0, %1, %2, %0;" : "+l"(acc[i][0]) : "l"(xp), "l"(wa.x));
                asm("fma.rn.f32x2 %0, %1, %2, %0;" : "+l"(acc[i][1]) : "l"(xp), "l"(wa.y));
                asm("fma.rn.f32x2 %0, %1, %2, %0;" : "+l"(acc[i][2]) : "l"(xp), "l"(wb.x));
                asm("fma.rn.f32x2 %0, %1, %2, %0;" : "+l"(acc[i][3]) : "l"(xp), "l"(wb.y));
            }
        }
        __syncthreads();
    }

    float bv[8];
    #pragma unroll
    for (int c = 0; c < 8; c++) bv[c] = bias ? bias[tx * 8 + c] : 0.f;
    #pragma unroll
    for (int i = 0; i < 8; i++) {
        int row = row0 + ty * 8 + i;
        if (row < n) {
            float o[8];
            #pragma unroll
            for (int p = 0; p < 4; p++) {
                float lo, hi;
                asm("mov.b64 {%0, %1}, %2;" : "=f"(lo), "=f"(hi) : "l"(acc[i][p]));
                o[2 * p]     = lo + bv[2 * p];
                o[2 * p + 1] = hi + bv[2 * p + 1];
            }
            *(float4*)&Y[(size_t)row * 128 + tx * 8]     = *(float4*)&o[0];
            *(float4*)&Y[(size_t)row * 128 + tx * 8 + 4] = *(float4*)&o[4];
        }
    }
}

// ---------------- aggregate: Y[i] = relu(sum_e nrm*H[src] + dinv_i^2*H[i] + b) ----------------
__global__ void aggregate_kernel(const float* __restrict__ H, const float* __restrict__ bias,
                                 float* __restrict__ Y) {
    int warp = (blockIdx.x * blockDim.x + threadIdx.x) >> 5;
    int lane = threadIdx.x & 31;
    if (warp >= NN) return;
    int beg = g_rowptr[warp];
    int end = g_rowptr[warp + 1];
    const float4* __restrict__ H4 = (const float4*)H;

    float4 acc = make_float4(0.f, 0.f, 0.f, 0.f);
    int e = beg;
    for (; e + 4 <= end; e += 4) {
        int   s0 = g_csr_src[e + 0], s1 = g_csr_src[e + 1];
        int   s2 = g_csr_src[e + 2], s3 = g_csr_src[e + 3];
        float n0 = g_csr_nrm[e + 0], n1 = g_csr_nrm[e + 1];
        float n2 = g_csr_nrm[e + 2], n3 = g_csr_nrm[e + 3];
        float4 h0 = __ldg(H4 + (size_t)s0 * 32 + lane);
        float4 h1 = __ldg(H4 + (size_t)s1 * 32 + lane);
        float4 h2 = __ldg(H4 + (size_t)s2 * 32 + lane);
        float4 h3 = __ldg(H4 + (size_t)s3 * 32 + lane);
        acc.x = fmaf(n0, h0.x, acc.x); acc.y = fmaf(n0, h0.y, acc.y);
        acc.z = fmaf(n0, h0.z, acc.z); acc.w = fmaf(n0, h0.w, acc.w);
        acc.x = fmaf(n1, h1.x, acc.x); acc.y = fmaf(n1, h1.y, acc.y);
        acc.z = fmaf(n1, h1.z, acc.z); acc.w = fmaf(n1, h1.w, acc.w);
        acc.x = fmaf(n2, h2.x, acc.x); acc.y = fmaf(n2, h2.y, acc.y);
        acc.z = fmaf(n2, h2.z, acc.z); acc.w = fmaf(n2, h2.w, acc.w);
        acc.x = fmaf(n3, h3.x, acc.x); acc.y = fmaf(n3, h3.y, acc.y);
        acc.z = fmaf(n3, h3.z, acc.z); acc.w = fmaf(n3, h3.w, acc.w);
    }
    for (; e < end; e++) {
        int s = g_csr_src[e];
        float nv = g_csr_nrm[e];
        float4 h = __ldg(H4 + (size_t)s * 32 + lane);
        acc.x = fmaf(nv, h.x, acc.x); acc.y = fmaf(nv, h.y, acc.y);
        acc.z = fmaf(nv, h.z, acc.z); acc.w = fmaf(nv, h.w, acc.w);
    }
    // self loop: norm = dinv^2 * 1
    float di = g_dinv[warp];
    float sn = di * di;
    float4 hs = __ldg(H4 + (size_t)warp * 32 + lane);
    acc.x = fmaf(sn, hs.x, acc.x); acc.y = fmaf(sn, hs.y, acc.y);
    acc.z = fmaf(sn, hs.z, acc.z); acc.w = fmaf(sn, hs.w, acc.w);

    float4 b = __ldg((const float4*)bias + lane);
    acc.x = fmaxf(acc.x + b.x, 0.f);
    acc.y = fmaxf(acc.y + b.y, 0.f);
    acc.z = fmaxf(acc.z + b.z, 0.f);
    acc.w = fmaxf(acc.w + b.w, 0.f);
    ((float4*)Y)[(size_t)warp * 32 + lane] = acc;
}

// ---------------- launch ----------------
extern "C" void kernel_launch(void* const* d_in, const int* in_sizes, int n_in,
                              void* d_out, int out_size) {
    // Identify inputs by element count (robust to metadata ordering).
    const float* x = nullptr;
    const float* ew = nullptr;
    const void*  ei = nullptr;
    const float* Ws[3] = {nullptr, nullptr, nullptr};   // W1, W2, Wfc in order
    const float* bs[3] = {nullptr, nullptr, nullptr};   // b1, b2, bfc in order
    int nW = 0, nb = 0;
    for (int i = 0; i < n_in; i++) {
        long long sz = in_sizes[i];
        if      (sz == (long long)NN * FD)  x  = (const float*)d_in[i];
        else if (sz == EE)                  ew = (const float*)d_in[i];
        else if (sz == 2LL * EE)            ei = d_in[i];
        else if (sz == FD * FD) { if (nW < 3) Ws[nW++] = (const float*)d_in[i]; }
        else if (sz == FD)      { if (nb < 3) bs[nb++] = (const float*)d_in[i]; }
    }
    const float *W1 = Ws[0], *W2 = Ws[1], *Wfc = Ws[2];
    const float *b1 = bs[0], *b2 = bs[1], *bfc = bs[2];
    float* out = (float*)d_out;

    float* hA; cudaGetSymbolAddress((void**)&hA, g_hA);
    float* hB; cudaGetSymbolAddress((void**)&hB, g_hB);

    // Side stream + events for fork-join (created once; no device allocation).
    static cudaStream_t s2 = nullptr;
    static cudaEvent_t evFork = nullptr, evJoin = nullptr;
    if (!s2) {
        cudaStreamCreateWithFlags(&s2, cudaStreamNonBlocking);
        cudaEventCreateWithFlags(&evFork, cudaEventDisableTiming);
        cudaEventCreateWithFlags(&evJoin, cudaEventDisableTiming);
    }

    int nodeBlocks = (NN + 255) / 256;
    int edgeBlocks = (EE + 255) / 256;
    int gemmBlocks = (NN + BM - 1) / BM;
    int aggBlocks  = (NN + 7) / 8;      // 8 warps/block

    // Fork: CSR/norm prep chain on s2, concurrent with GEMM1 on main stream.
    cudaEventRecord(evFork, 0);
    cudaStreamWaitEvent(s2, evFork, 0);

    init_kernel<<<nodeBlocks, 256, 0, s2>>>((const unsigned int*)ei);
    deg_kernel<<<edgeBlocks, 256, 0, s2>>>(ei, ew);
    scan1_kernel<<<SCAN_NB, SCAN_B, 0, s2>>>();
    scan2_kernel<<<1, 128, 0, s2>>>();
    scan3_kernel<<<nodeBlocks, 256, 0, s2>>>();
    csr_kernel<<<edgeBlocks, 256, 0, s2>>>(ei, ew);
    cudaEventRecord(evJoin, s2);

    // GEMM1 runs concurrently with prep (depends only on x, W1).
    gemm_kernel<<<gemmBlocks, 256>>>(x, W1, nullptr, hA, NN);

    // Join: aggregation needs both GEMM1 output and the CSR.
    cudaStreamWaitEvent(0, evJoin, 0);

    aggregate_kernel<<<aggBlocks, 256>>>(hA, b1, hB);
    gemm_kernel<<<gemmBlocks, 256>>>(hB, W2, nullptr, hA, NN);
    aggregate_kernel<<<aggBlocks, 256>>>(hA, b2, hB);
    gemm_kernel<<<gemmBlocks, 256>>>(hB, Wfc, bfc, out, NN);
}

// round 6
// speedup vs baseline: 1.3279x; 1.0960x over previous
#include <cuda_runtime.h>
#include <cuda_fp16.h>
#include <cstdint>
#include <cstddef>

#define NN 50000
#define EE 800000
#define FD 128
#define SCAN_B 512
#define SCAN_NB 98   // ceil(50000/512)

// ---------------- scratch (static device globals; no runtime alloc) ----------------
__device__ int    g_is64;               // 1 if edge_index is int64, 0 if int32
__device__ float  g_dinv[NN];           // deg -> rsqrt(deg)
__device__ int    g_cnt[NN];            // histogram, then write-cursor
__device__ int    g_rowptr[NN + 1];
__device__ int    g_blocksum[SCAN_NB];
__device__ int    g_blockoff[SCAN_NB];
__device__ int    g_csr_src[EE];
__device__ float  g_csr_nrm[EE];
__device__ __half g_hHalf[(size_t)NN * FD];   // fp16 gather source (GEMM output)
__device__ float  g_hF[(size_t)NN * FD];      // fp32 aggregate output (GEMM input)

// ---------------- dtype helpers ----------------
__device__ __forceinline__ int edge_at(const void* ei, long long pos) {
    if (g_is64) return (int)((const long long*)ei)[pos];
    return ((const int*)ei)[pos];
}

// ---------------- init (+dtype detect in block 0) ----------------
// int64 edge values < 2^31 => every odd 32-bit word is 0. int32 data: odd words
// are random node ids; P(first 32 odd words all zero) is negligible.
__global__ void init_kernel(const unsigned int* __restrict__ w) {
    int i = blockIdx.x * blockDim.x + threadIdx.x;
    if (blockIdx.x == 0 && threadIdx.x < 32) {
        unsigned int v = w[2 * threadIdx.x + 1];
        unsigned int all0 = __ballot_sync(0xffffffffu, v == 0u);
        if (threadIdx.x == 0) g_is64 = (all0 == 0xffffffffu) ? 1 : 0;
    }
    if (i < NN) { g_dinv[i] = 1.0f; g_cnt[i] = 0; }   // deg starts at 1 (self loop)
}

__global__ void deg_kernel(const void* __restrict__ ei, const float* __restrict__ ew) {
    int e = blockIdx.x * blockDim.x + threadIdx.x;
    if (e < EE) {
        int d = edge_at(ei, (long long)EE + e);
        atomicAdd(&g_dinv[d], ew[e]);
        atomicAdd(&g_cnt[d], 1);
    }
}

// ---------------- exclusive scan of g_cnt -> g_rowptr ----------------
__global__ void scan1_kernel() {
    __shared__ int s[SCAN_B];
    int t = threadIdx.x;
    int i = blockIdx.x * SCAN_B + t;
    int v = (i < NN) ? g_cnt[i] : 0;
    s[t] = v;
    __syncthreads();
    for (int off = 1; off < SCAN_B; off <<= 1) {
        int tmp = (t >= off) ? s[t - off] : 0;
        __syncthreads();
        s[t] += tmp;
        __syncthreads();
    }
    if (i < NN) g_rowptr[i] = s[t] - v;
    if (t == SCAN_B - 1) g_blocksum[blockIdx.x] = s[t];
}

__global__ void scan2_kernel() {
    __shared__ int s[128];
    int t = threadIdx.x;
    int v = (t < SCAN_NB) ? g_blocksum[t] : 0;
    s[t] = v;
    __syncthreads();
    for (int off = 1; off < 128; off <<= 1) {
        int tmp = (t >= off) ? s[t - off] : 0;
        __syncthreads();
        s[t] += tmp;
        __syncthreads();
    }
    if (t < SCAN_NB) g_blockoff[t] = s[t] - v;
}

// scan3 also performs the deg -> rsqrt(deg) conversion (deg complete by now)
__global__ void scan3_kernel() {
    int i = blockIdx.x * blockDim.x + threadIdx.x;
    if (i < NN) {
        int v = g_rowptr[i] + g_blockoff[i / SCAN_B];
        g_rowptr[i] = v;
        g_cnt[i] = v;
        g_dinv[i] = rsqrtf(g_dinv[i]);
    }
    if (i == 0) g_rowptr[NN] = EE;
}

// ---------------- CSR build (edges bucketed by dst) ----------------
__global__ void csr_kernel(const void* __restrict__ ei, const float* __restrict__ ew) {
    int e = blockIdx.x * blockDim.x + threadIdx.x;
    if (e < EE) {
        int s = edge_at(ei, e);
        int d = edge_at(ei, (long long)EE + e);
        float nrm = g_dinv[s] * ew[e] * g_dinv[d];
        int pos = atomicAdd(&g_cnt[d], 1);
        g_csr_src[pos] = s;
        g_csr_nrm[pos] = nrm;
    }
}

// ---------------- GEMM: Y[n,128] = X[n,128] @ W[128,128] (+bias) ----------------
// 128x128 tile, 256 threads, 8x8 micro-tile, packed fma.rn.f32x2 accumulators.
// OutT = __half (feeds gather) or float (final output).
#define BM 128
template <typename OutT>
__global__ __launch_bounds__(256) void gemm_kernel(const float* __restrict__ X,
                                                   const float* __restrict__ W,
                                                   const float* __restrict__ bias,
                                                   OutT* __restrict__ Y, int n) {
    __shared__ float sX[BM][16];
    __shared__ float sW[16][128];
    int tid = threadIdx.x;
    int tx = tid & 15;                // col group: cols tx*8 .. tx*8+7
    int ty = tid >> 4;                // row group: rows ty*8 .. ty*8+7
    int row0 = blockIdx.x * BM;

    unsigned long long acc[8][4];     // 8 rows x 4 packed col-pairs
    #pragma unroll
    for (int i = 0; i < 8; i++)
        #pragma unroll
        for (int p = 0; p < 4; p++) acc[i][p] = 0ull;

    for (int kt = 0; kt < 8; kt++) {
        // stage W tile 16x128 (512 float4, 2 per thread)
        #pragma unroll
        for (int j = 0; j < 2; j++) {
            int i4 = tid + 256 * j;
            int r = i4 >> 5, c = (i4 & 31) << 2;
            *(float4*)&sW[r][c] = *(const float4*)&W[(kt * 16 + r) * 128 + c];
        }
        // stage X tile 128x16 (512 float4, 2 per thread)
        #pragma unroll
        for (int j = 0; j < 2; j++) {
            int i4 = tid + 256 * j;
            int r = i4 >> 2, c = (i4 & 3) << 2;
            float4 v = make_float4(0.f, 0.f, 0.f, 0.f);
            if (row0 + r < n)
                v = *(const float4*)&X[(size_t)(row0 + r) * 128 + kt * 16 + c];
            *(float4*)&sX[r][c] = v;
        }
        __syncthreads();
        #pragma unroll
        for (int kk = 0; kk < 16; kk++) {
            ulonglong2 wa = *(ulonglong2*)&sW[kk][tx * 8];
            ulonglong2 wb = *(ulonglong2*)&sW[kk][tx * 8 + 4];
            #pragma unroll
            for (int i = 0; i < 8; i++) {
                float xv = sX[ty * 8 + i][kk];
                unsigned long long xp;
                asm("mov.b64 %0, {%1, %1};" : "=l"(xp) : "f"(xv));
                asm("fma.rn.f32x2 %0, %1, %2, %0;" : "+l"(acc[i][0]) : "l"(xp), "l"(wa.x));
                asm("fma.rn.f32x2 %0, %1, %2, %0;" : "+l"(acc[i][1]) : "l"(xp), "l"(wa.y));
                asm("fma.rn.f32x2 %0, %1, %2, %0;" : "+l"(acc[i][2]) : "l"(xp), "l"(wb.x));
                asm("fma.rn.f32x2 %0, %1, %2, %0;" : "+l"(acc[i][3]) : "l"(xp), "l"(wb.y));
            }
        }
        __syncthreads();
    }

    float bv[8];
    #pragma unroll
    for (int c = 0; c < 8; c++) bv[c] = bias ? bias[tx * 8 + c] : 0.f;
    #pragma unroll
    for (int i = 0; i < 8; i++) {
        int row = row0 + ty * 8 + i;
        if (row < n) {
            float o[8];
            #pragma unroll
            for (int p = 0; p < 4; p++) {
                float lo, hi;
                asm("mov.b64 {%0, %1}, %2;" : "=f"(lo), "=f"(hi) : "l"(acc[i][p]));
                o[2 * p]     = lo + bv[2 * p];
                o[2 * p + 1] = hi + bv[2 * p + 1];
            }
            if (sizeof(OutT) == 2) {
                // pack 8 halfs = 16 bytes
                __half h[8];
                #pragma unroll
                for (int c = 0; c < 8; c++) h[c] = __float2half_rn(o[c]);
                *(uint4*)&((__half*)Y)[(size_t)row * 128 + tx * 8] = *(uint4*)&h[0];
            } else {
                *(float4*)&((float*)Y)[(size_t)row * 128 + tx * 8]     = *(float4*)&o[0];
                *(float4*)&((float*)Y)[(size_t)row * 128 + tx * 8 + 4] = *(float4*)&o[4];
            }
        }
    }
}

// ---------------- aggregate: Y[i] = relu(sum_e nrm*H[src] + dinv_i^2*H[i] + b) ----------------
// H is fp16 (halves L2 gather traffic); accumulation fp32; Y fp32.
__device__ __forceinline__ void acc_edge(float4& acc, float nv, uint2 v) {
    __half2* ph = (__half2*)&v;
    float2 f01 = __half22float2(ph[0]);
    float2 f23 = __half22float2(ph[1]);
    acc.x = fmaf(nv, f01.x, acc.x);
    acc.y = fmaf(nv, f01.y, acc.y);
    acc.z = fmaf(nv, f23.x, acc.z);
    acc.w = fmaf(nv, f23.y, acc.w);
}

__global__ void aggregate_kernel(const __half* __restrict__ H, const float* __restrict__ bias,
                                 float* __restrict__ Y) {
    int warp = (blockIdx.x * blockDim.x + threadIdx.x) >> 5;
    int lane = threadIdx.x & 31;
    if (warp >= NN) return;
    int beg = g_rowptr[warp];
    int end = g_rowptr[warp + 1];
    const uint2* __restrict__ H2 = (const uint2*)H;   // 4 halfs per uint2; 32 lanes cover 128 cols

    float4 acc = make_float4(0.f, 0.f, 0.f, 0.f);
    int e = beg;
    for (; e + 4 <= end; e += 4) {
        int   s0 = g_csr_src[e + 0], s1 = g_csr_src[e + 1];
        int   s2 = g_csr_src[e + 2], s3 = g_csr_src[e + 3];
        float n0 = g_csr_nrm[e + 0], n1 = g_csr_nrm[e + 1];
        float n2 = g_csr_nrm[e + 2], n3 = g_csr_nrm[e + 3];
        uint2 v0 = __ldg(H2 + (size_t)s0 * 32 + lane);
        uint2 v1 = __ldg(H2 + (size_t)s1 * 32 + lane);
        uint2 v2 = __ldg(H2 + (size_t)s2 * 32 + lane);
        uint2 v3 = __ldg(H2 + (size_t)s3 * 32 + lane);
        acc_edge(acc, n0, v0);
        acc_edge(acc, n1, v1);
        acc_edge(acc, n2, v2);
        acc_edge(acc, n3, v3);
    }
    for (; e < end; e++) {
        int s = g_csr_src[e];
        float nv = g_csr_nrm[e];
        uint2 v = __ldg(H2 + (size_t)s * 32 + lane);
        acc_edge(acc, nv, v);
    }
    // self loop: norm = dinv^2 * 1
    float di = g_dinv[warp];
    float sn = di * di;
    uint2 vs = __ldg(H2 + (size_t)warp * 32 + lane);
    acc_edge(acc, sn, vs);

    float4 b = __ldg((const float4*)bias + lane);
    acc.x = fmaxf(acc.x + b.x, 0.f);
    acc.y = fmaxf(acc.y + b.y, 0.f);
    acc.z = fmaxf(acc.z + b.z, 0.f);
    acc.w = fmaxf(acc.w + b.w, 0.f);
    ((float4*)Y)[(size_t)warp * 32 + lane] = acc;
}

// ---------------- launch ----------------
extern "C" void kernel_launch(void* const* d_in, const int* in_sizes, int n_in,
                              void* d_out, int out_size) {
    // Identify inputs by element count (robust to metadata ordering).
    const float* x = nullptr;
    const float* ew = nullptr;
    const void*  ei = nullptr;
    const float* Ws[3] = {nullptr, nullptr, nullptr};   // W1, W2, Wfc in order
    const float* bs[3] = {nullptr, nullptr, nullptr};   // b1, b2, bfc in order
    int nW = 0, nb = 0;
    for (int i = 0; i < n_in; i++) {
        long long sz = in_sizes[i];
        if      (sz == (long long)NN * FD)  x  = (const float*)d_in[i];
        else if (sz == EE)                  ew = (const float*)d_in[i];
        else if (sz == 2LL * EE)            ei = d_in[i];
        else if (sz == FD * FD) { if (nW < 3) Ws[nW++] = (const float*)d_in[i]; }
        else if (sz == FD)      { if (nb < 3) bs[nb++] = (const float*)d_in[i]; }
    }
    const float *W1 = Ws[0], *W2 = Ws[1], *Wfc = Ws[2];
    const float *b1 = bs[0], *b2 = bs[1], *bfc = bs[2];
    float* out = (float*)d_out;

    __half* hH; cudaGetSymbolAddress((void**)&hH, g_hHalf);
    float*  hF; cudaGetSymbolAddress((void**)&hF, g_hF);

    // Side stream + events for fork-join (created once; no device allocation).
    static cudaStream_t s2 = nullptr;
    static cudaEvent_t evFork = nullptr, evJoin = nullptr;
    if (!s2) {
        cudaStreamCreateWithFlags(&s2, cudaStreamNonBlocking);
        cudaEventCreateWithFlags(&evFork, cudaEventDisableTiming);
        cudaEventCreateWithFlags(&evJoin, cudaEventDisableTiming);
    }

    int nodeBlocks = (NN + 255) / 256;
    int edgeBlocks = (EE + 255) / 256;
    int gemmBlocks = (NN + BM - 1) / BM;
    int aggBlocks  = (NN + 7) / 8;      // 8 warps/block

    // Fork: CSR/norm prep chain on s2, concurrent with GEMM1 on main stream.
    cudaEventRecord(evFork, 0);
    cudaStreamWaitEvent(s2, evFork, 0);

    init_kernel<<<nodeBlocks, 256, 0, s2>>>((const unsigned int*)ei);
    deg_kernel<<<edgeBlocks, 256, 0, s2>>>(ei, ew);
    scan1_kernel<<<SCAN_NB, SCAN_B, 0, s2>>>();
    scan2_kernel<<<1, 128, 0, s2>>>();
    scan3_kernel<<<nodeBlocks, 256, 0, s2>>>();
    csr_kernel<<<edgeBlocks, 256, 0, s2>>>(ei, ew);
    cudaEventRecord(evJoin, s2);

    // GEMM1 runs concurrently with prep (depends only on x, W1). Output fp16.
    gemm_kernel<__half><<<gemmBlocks, 256>>>(x, W1, nullptr, hH, NN);

    // Join: aggregation needs both GEMM1 output and the CSR.
    cudaStreamWaitEvent(0, evJoin, 0);

    aggregate_kernel<<<aggBlocks, 256>>>(hH, b1, hF);
    gemm_kernel<__half><<<gemmBlocks, 256>>>(hF, W2, nullptr, hH, NN);
    aggregate_kernel<<<aggBlocks, 256>>>(hH, b2, hF);
    gemm_kernel<float><<<gemmBlocks, 256>>>(hF, Wfc, bfc, out, NN);
}

// round 7
// speedup vs baseline: 1.4146x; 1.0653x over previous
#include <cuda_runtime.h>
#include <cuda_fp16.h>
#include <cstdint>
#include <cstddef>

#define NN 50000
#define EE 800000
#define FD 128
#define SCAN_B 512
#define SCAN_NB 98   // ceil(50000/512)

// ---------------- scratch (static device globals; no runtime alloc) ----------------
__device__ int    g_is64;               // 1 if edge_index is int64, 0 if int32
__device__ float  g_dinv[NN];           // deg -> rsqrt(deg)
__device__ int    g_cnt[NN];            // histogram, then write-cursor
__device__ int    g_rowptr[NN + 1];
__device__ int    g_blocksum[SCAN_NB];
__device__ int    g_blockoff[SCAN_NB];
__device__ int    g_csr_src[EE];
__device__ float  g_csr_nrm[EE];
__device__ __half g_hHalf[(size_t)NN * FD];   // fp16 gather source (GEMM output)
__device__ float  g_hF[(size_t)NN * FD];      // fp32 aggregate output (GEMM input)

// ---------------- dtype helpers ----------------
__device__ __forceinline__ int edge_at(const void* ei, long long pos) {
    if (g_is64) return (int)((const long long*)ei)[pos];
    return ((const int*)ei)[pos];
}

// ---------------- init (+dtype detect in block 0) ----------------
__global__ void init_kernel(const unsigned int* __restrict__ w) {
    int i = blockIdx.x * blockDim.x + threadIdx.x;
    if (blockIdx.x == 0 && threadIdx.x < 32) {
        unsigned int v = w[2 * threadIdx.x + 1];
        unsigned int all0 = __ballot_sync(0xffffffffu, v == 0u);
        if (threadIdx.x == 0) g_is64 = (all0 == 0xffffffffu) ? 1 : 0;
    }
    if (i < NN) { g_dinv[i] = 1.0f; g_cnt[i] = 0; }   // deg starts at 1 (self loop)
}

__global__ void deg_kernel(const void* __restrict__ ei, const float* __restrict__ ew) {
    int e = blockIdx.x * blockDim.x + threadIdx.x;
    if (e < EE) {
        int d = edge_at(ei, (long long)EE + e);
        atomicAdd(&g_dinv[d], ew[e]);
        atomicAdd(&g_cnt[d], 1);
    }
}

// ---------------- exclusive scan of g_cnt -> g_rowptr ----------------
__global__ void scan1_kernel() {
    __shared__ int s[SCAN_B];
    int t = threadIdx.x;
    int i = blockIdx.x * SCAN_B + t;
    int v = (i < NN) ? g_cnt[i] : 0;
    s[t] = v;
    __syncthreads();
    for (int off = 1; off < SCAN_B; off <<= 1) {
        int tmp = (t >= off) ? s[t - off] : 0;
        __syncthreads();
        s[t] += tmp;
        __syncthreads();
    }
    if (i < NN) g_rowptr[i] = s[t] - v;
    if (t == SCAN_B - 1) g_blocksum[blockIdx.x] = s[t];
}

__global__ void scan2_kernel() {
    __shared__ int s[128];
    int t = threadIdx.x;
    int v = (t < SCAN_NB) ? g_blocksum[t] : 0;
    s[t] = v;
    __syncthreads();
    for (int off = 1; off < 128; off <<= 1) {
        int tmp = (t >= off) ? s[t - off] : 0;
        __syncthreads();
        s[t] += tmp;
        __syncthreads();
    }
    if (t < SCAN_NB) g_blockoff[t] = s[t] - v;
}

__global__ void scan3_kernel() {
    int i = blockIdx.x * blockDim.x + threadIdx.x;
    if (i < NN) {
        int v = g_rowptr[i] + g_blockoff[i / SCAN_B];
        g_rowptr[i] = v;
        g_cnt[i] = v;
        g_dinv[i] = rsqrtf(g_dinv[i]);
    }
    if (i == 0) g_rowptr[NN] = EE;
}

// ---------------- CSR build (edges bucketed by dst) ----------------
__global__ void csr_kernel(const void* __restrict__ ei, const float* __restrict__ ew) {
    int e = blockIdx.x * blockDim.x + threadIdx.x;
    if (e < EE) {
        int s = edge_at(ei, e);
        int d = edge_at(ei, (long long)EE + e);
        float nrm = g_dinv[s] * ew[e] * g_dinv[d];
        int pos = atomicAdd(&g_cnt[d], 1);
        g_csr_src[pos] = s;
        g_csr_nrm[pos] = nrm;
    }
}

// ---------------- tensor-core GEMM (legacy mma.sync HMMA path) ----------------
// Y[n,128] = X[n,128] @ W[128,128] (+bias), dual-fp16 split for ~fp32 precision:
// X = Xhi + Xlo, W = Whi + Wlo; D = Xhi*Whi + Xhi*Wlo + Xlo*Whi (fp32 accum).
#define BM 128
#define LDA 136                           // 128 + 8 pad halfs -> 272B rows, LDSM conflict-free
#define TILE_BYTES (128 * LDA * 2)        // 34816
#define OFF_AHI 0
#define OFF_ALO (TILE_BYTES)
#define OFF_BHI (2 * TILE_BYTES)
#define OFF_BLO (3 * TILE_BYTES)
#define S_GEMM  (4 * TILE_BYTES)          // 139264 B dynamic smem

__device__ __forceinline__ uint32_t smem_u32(const void* p) {
    uint32_t a;
    asm("{ .reg .u64 t; cvta.to.shared.u64 t, %1; cvt.u32.u64 %0, t; }" : "=r"(a) : "l"(p));
    return a;
}

#define LDSM4(R, addr) \
    asm volatile("ldmatrix.sync.aligned.m8n8.x4.shared.b16 {%0,%1,%2,%3}, [%4];" \
        : "=r"((R)[0]), "=r"((R)[1]), "=r"((R)[2]), "=r"((R)[3]) : "r"(addr))

#define MMA16816(D, A, B0, B1) \
    asm volatile("mma.sync.aligned.m16n8k16.row.col.f32.f16.f16.f32 " \
        "{%0,%1,%2,%3}, {%4,%5,%6,%7}, {%8,%9}, {%0,%1,%2,%3};" \
        : "+f"((D)[0]), "+f"((D)[1]), "+f"((D)[2]), "+f"((D)[3]) \
        : "r"((A)[0]), "r"((A)[1]), "r"((A)[2]), "r"((A)[3]), "r"(B0), "r"(B1))

__device__ __forceinline__ void split2(float x, __half& hi, __half& lo) {
    hi = __float2half_rn(x);
    lo = __float2half_rn(x - __half2float(hi));
}

template <typename OutT>
__global__ __launch_bounds__(256) void gemm_mma_kernel(const float* __restrict__ X,
                                                       const float* __restrict__ W,
                                                       const float* __restrict__ bias,
                                                       OutT* __restrict__ Y, int n) {
    extern __shared__ char smem[];
    uint32_t sb = smem_u32(smem);
    int tid = threadIdx.x;
    int lane = tid & 31;
    int wid = tid >> 5;
    int row0 = blockIdx.x * BM;

    __half* Ahi = (__half*)(smem + OFF_AHI);
    __half* Alo = (__half*)(smem + OFF_ALO);
    __half* Bhi = (__half*)(smem + OFF_BHI);
    __half* Blo = (__half*)(smem + OFF_BLO);

    // ---- stage X tile (rows row0..row0+127) as hi/lo fp16 ----
    #pragma unroll
    for (int j = 0; j < 16; j++) {
        int i4 = tid + 256 * j;               // 0..4095 float4s
        int row = i4 >> 5;
        int c4 = (i4 & 31) << 2;
        float4 v = make_float4(0.f, 0.f, 0.f, 0.f);
        if (row0 + row < n)
            v = *(const float4*)&X[(size_t)(row0 + row) * 128 + c4];
        __half h[4], l[4];
        split2(v.x, h[0], l[0]); split2(v.y, h[1], l[1]);
        split2(v.z, h[2], l[2]); split2(v.w, h[3], l[3]);
        *(uint2*)&Ahi[row * LDA + c4] = *(uint2*)h;
        *(uint2*)&Alo[row * LDA + c4] = *(uint2*)l;
    }
    // ---- stage W^T: Bsm[ncol][k] = W[k][ncol], hi/lo ----
    #pragma unroll
    for (int j = 0; j < 16; j++) {
        int i4 = tid + 256 * j;
        int k = i4 >> 5;
        int n4 = (i4 & 31) << 2;
        float4 v = *(const float4*)&W[(size_t)k * 128 + n4];
        float vv[4] = {v.x, v.y, v.z, v.w};
        #pragma unroll
        for (int e = 0; e < 4; e++) {
            __half hh, ll;
            split2(vv[e], hh, ll);
            Bhi[(n4 + e) * LDA + k] = hh;
            Blo[(n4 + e) * LDA + k] = ll;
        }
    }
    __syncthreads();

    // ---- warp tiling: 8 warps = 4(M) x 2(N); warp tile 32x64 ----
    int wm = wid & 3;                     // rows wm*32 .. +31
    int wn = wid >> 2;                    // cols wn*64 .. +63
    int m_base = wm * 32, n_base = wn * 64;

    float d[2][8][4];
    #pragma unroll
    for (int mt = 0; mt < 2; mt++)
        #pragma unroll
        for (int nt = 0; nt < 8; nt++)
            #pragma unroll
            for (int q = 0; q < 4; q++) d[mt][nt][q] = 0.f;

    // ldmatrix per-lane element offsets
    int aRow = lane & 15, aK = (lane >> 4) << 3;
    int bRow = (lane & 7) + ((lane >> 4) << 3), bK = ((lane >> 3) & 1) << 3;

    uint32_t sAhi = sb + OFF_AHI, sAlo = sb + OFF_ALO;
    uint32_t sBhi = sb + OFF_BHI, sBlo = sb + OFF_BLO;

    #pragma unroll
    for (int ks = 0; ks < 8; ks++) {
        int k0 = ks * 16;
        uint32_t ah[2][4], al[2][4];
        #pragma unroll
        for (int mt = 0; mt < 2; mt++) {
            uint32_t off = (uint32_t)((m_base + mt * 16 + aRow) * LDA + k0 + aK) * 2;
            LDSM4(ah[mt], sAhi + off);
            LDSM4(al[mt], sAlo + off);
        }
        uint32_t bh[4][4], bl[4][4];      // each covers 2 n-tiles: {nt0.b0, nt0.b1, nt1.b0, nt1.b1}
        #pragma unroll
        for (int bt = 0; bt < 4; bt++) {
            uint32_t off = (uint32_t)((n_base + bt * 16 + bRow) * LDA + k0 + bK) * 2;
            LDSM4(bh[bt], sBhi + off);
            LDSM4(bl[bt], sBlo + off);
        }
        #pragma unroll
        for (int mt = 0; mt < 2; mt++)
            #pragma unroll
            for (int bt = 0; bt < 4; bt++)
                #pragma unroll
                for (int h = 0; h < 2; h++) {
                    int nt = bt * 2 + h;
                    MMA16816(d[mt][nt], ah[mt], bh[bt][2 * h], bh[bt][2 * h + 1]); // hi*hi
                    MMA16816(d[mt][nt], ah[mt], bl[bt][2 * h], bl[bt][2 * h + 1]); // hi*lo
                    MMA16816(d[mt][nt], al[mt], bh[bt][2 * h], bh[bt][2 * h + 1]); // lo*hi
                }
    }

    // ---- epilogue ----
    #pragma unroll
    for (int mt = 0; mt < 2; mt++) {
        int rlo = row0 + m_base + mt * 16 + (lane >> 2);
        int rhi = rlo + 8;
        #pragma unroll
        for (int nt = 0; nt < 8; nt++) {
            int c = n_base + nt * 8 + (lane & 3) * 2;
            float b0 = bias ? __ldg(&bias[c]) : 0.f;
            float b1 = bias ? __ldg(&bias[c + 1]) : 0.f;
            float v0 = d[mt][nt][0] + b0, v1 = d[mt][nt][1] + b1;
            float v2 = d[mt][nt][2] + b0, v3 = d[mt][nt][3] + b1;
            if (sizeof(OutT) == 2) {
                if (rlo < n) *(__half2*)&((__half*)Y)[(size_t)rlo * 128 + c] = __floats2half2_rn(v0, v1);
                if (rhi < n) *(__half2*)&((__half*)Y)[(size_t)rhi * 128 + c] = __floats2half2_rn(v2, v3);
            } else {
                if (rlo < n) *(float2*)&((float*)Y)[(size_t)rlo * 128 + c] = make_float2(v0, v1);
                if (rhi < n) *(float2*)&((float*)Y)[(size_t)rhi * 128 + c] = make_float2(v2, v3);
            }
        }
    }
}

// ---------------- aggregate: Y[i] = relu(sum_e nrm*H[src] + dinv_i^2*H[i] + b) ----------------
__device__ __forceinline__ void acc_edge(float4& acc, float nv, uint2 v) {
    __half2* ph = (__half2*)&v;
    float2 f01 = __half22float2(ph[0]);
    float2 f23 = __half22float2(ph[1]);
    acc.x = fmaf(nv, f01.x, acc.x);
    acc.y = fmaf(nv, f01.y, acc.y);
    acc.z = fmaf(nv, f23.x, acc.z);
    acc.w = fmaf(nv, f23.y, acc.w);
}

__global__ void aggregate_kernel(const __half* __restrict__ H, const float* __restrict__ bias,
                                 float* __restrict__ Y) {
    int warp = (blockIdx.x * blockDim.x + threadIdx.x) >> 5;
    int lane = threadIdx.x & 31;
    if (warp >= NN) return;
    int beg = g_rowptr[warp];
    int end = g_rowptr[warp + 1];
    const uint2* __restrict__ H2 = (const uint2*)H;

    float4 acc = make_float4(0.f, 0.f, 0.f, 0.f);
    int e = beg;
    for (; e + 4 <= end; e += 4) {
        int   s0 = g_csr_src[e + 0], s1 = g_csr_src[e + 1];
        int   s2 = g_csr_src[e + 2], s3 = g_csr_src[e + 3];
        float n0 = g_csr_nrm[e + 0], n1 = g_csr_nrm[e + 1];
        float n2 = g_csr_nrm[e + 2], n3 = g_csr_nrm[e + 3];
        uint2 v0 = __ldg(H2 + (size_t)s0 * 32 + lane);
        uint2 v1 = __ldg(H2 + (size_t)s1 * 32 + lane);
        uint2 v2 = __ldg(H2 + (size_t)s2 * 32 + lane);
        uint2 v3 = __ldg(H2 + (size_t)s3 * 32 + lane);
        acc_edge(acc, n0, v0);
        acc_edge(acc, n1, v1);
        acc_edge(acc, n2, v2);
        acc_edge(acc, n3, v3);
    }
    for (; e < end; e++) {
        int s = g_csr_src[e];
        float nv = g_csr_nrm[e];
        uint2 v = __ldg(H2 + (size_t)s * 32 + lane);
        acc_edge(acc, nv, v);
    }
    float di = g_dinv[warp];
    float sn = di * di;
    uint2 vs = __ldg(H2 + (size_t)warp * 32 + lane);
    acc_edge(acc, sn, vs);

    float4 b = __ldg((const float4*)bias + lane);
    acc.x = fmaxf(acc.x + b.x, 0.f);
    acc.y = fmaxf(acc.y + b.y, 0.f);
    acc.z = fmaxf(acc.z + b.z, 0.f);
    acc.w = fmaxf(acc.w + b.w, 0.f);
    ((float4*)Y)[(size_t)warp * 32 + lane] = acc;
}

// ---------------- launch ----------------
extern "C" void kernel_launch(void* const* d_in, const int* in_sizes, int n_in,
                              void* d_out, int out_size) {
    const float* x = nullptr;
    const float* ew = nullptr;
    const void*  ei = nullptr;
    const float* Ws[3] = {nullptr, nullptr, nullptr};
    const float* bs[3] = {nullptr, nullptr, nullptr};
    int nW = 0, nb = 0;
    for (int i = 0; i < n_in; i++) {
        long long sz = in_sizes[i];
        if      (sz == (long long)NN * FD)  x  = (const float*)d_in[i];
        else if (sz == EE)                  ew = (const float*)d_in[i];
        else if (sz == 2LL * EE)            ei = d_in[i];
        else if (sz == FD * FD) { if (nW < 3) Ws[nW++] = (const float*)d_in[i]; }
        else if (sz == FD)      { if (nb < 3) bs[nb++] = (const float*)d_in[i]; }
    }
    const float *W1 = Ws[0], *W2 = Ws[1], *Wfc = Ws[2];
    const float *b1 = bs[0], *b2 = bs[1], *bfc = bs[2];
    float* out = (float*)d_out;

    __half* hH; cudaGetSymbolAddress((void**)&hH, g_hHalf);
    float*  hF; cudaGetSymbolAddress((void**)&hF, g_hF);

    static cudaStream_t s2 = nullptr;
    static cudaEvent_t evFork = nullptr, evJoin = nullptr;
    if (!s2) {
        cudaStreamCreateWithFlags(&s2, cudaStreamNonBlocking);
        cudaEventCreateWithFlags(&evFork, cudaEventDisableTiming);
        cudaEventCreateWithFlags(&evJoin, cudaEventDisableTiming);
        cudaFuncSetAttribute(gemm_mma_kernel<__half>,
                             cudaFuncAttributeMaxDynamicSharedMemorySize, S_GEMM);
        cudaFuncSetAttribute(gemm_mma_kernel<float>,
                             cudaFuncAttributeMaxDynamicSharedMemorySize, S_GEMM);
    }

    int nodeBlocks = (NN + 255) / 256;
    int edgeBlocks = (EE + 255) / 256;
    int gemmBlocks = (NN + BM - 1) / BM;
    int aggBlocks  = (NN + 7) / 8;

    cudaEventRecord(evFork, 0);
    cudaStreamWaitEvent(s2, evFork, 0);

    init_kernel<<<nodeBlocks, 256, 0, s2>>>((const unsigned int*)ei);
    deg_kernel<<<edgeBlocks, 256, 0, s2>>>(ei, ew);
    scan1_kernel<<<SCAN_NB, SCAN_B, 0, s2>>>();
    scan2_kernel<<<1, 128, 0, s2>>>();
    scan3_kernel<<<nodeBlocks, 256, 0, s2>>>();
    csr_kernel<<<edgeBlocks, 256, 0, s2>>>(ei, ew);
    cudaEventRecord(evJoin, s2);

    // GEMM1 overlaps prep (depends only on x, W1). Output fp16.
    gemm_mma_kernel<__half><<<gemmBlocks, 256, S_GEMM>>>(x, W1, nullptr, hH, NN);

    cudaStreamWaitEvent(0, evJoin, 0);

    aggregate_kernel<<<aggBlocks, 256>>>(hH, b1, hF);
    gemm_mma_kernel<__half><<<gemmBlocks, 256, S_GEMM>>>(hF, W2, nullptr, hH, NN);
    aggregate_kernel<<<aggBlocks, 256>>>(hH, b2, hF);
    gemm_mma_kernel<float><<<gemmBlocks, 256, S_GEMM>>>(hF, Wfc, bfc, out, NN);
}

// round 8
// speedup vs baseline: 2.2685x; 1.6036x over previous
#include <cuda_runtime.h>
#include <cuda_fp16.h>
#include <cstdint>
#include <cstddef>

#define NN 50000
#define EE 800000
#define FD 128
#define SCAN_B 512
#define SCAN_NB 98   // ceil(50000/512)

// ---------------- scratch (static device globals; no runtime alloc) ----------------
__device__ int    g_is64;               // 1 if edge_index is int64, 0 if int32
__device__ float  g_dinv[NN];           // deg -> rsqrt(deg)
__device__ int    g_cnt[NN];            // histogram, then write-cursor
__device__ int    g_rowptr[NN + 1];
__device__ int    g_blocksum[SCAN_NB];
__device__ int    g_csr_src[EE];
__device__ float  g_csr_nrm[EE];
__device__ __half g_hA16[(size_t)NN * FD];    // GEMM output (gather source)
__device__ __half g_hB16[(size_t)NN * FD];    // aggregate output (GEMM input)

// ---------------- dtype helpers ----------------
__device__ __forceinline__ int edge_at(const void* ei, long long pos) {
    if (g_is64) return (int)((const long long*)ei)[pos];
    return ((const int*)ei)[pos];
}

// ---------------- init (+dtype detect in block 0) ----------------
__global__ void init_kernel(const unsigned int* __restrict__ w) {
    int i = blockIdx.x * blockDim.x + threadIdx.x;
    if (blockIdx.x == 0 && threadIdx.x < 32) {
        unsigned int v = w[2 * threadIdx.x + 1];
        unsigned int all0 = __ballot_sync(0xffffffffu, v == 0u);
        if (threadIdx.x == 0) g_is64 = (all0 == 0xffffffffu) ? 1 : 0;
    }
    if (i < NN) { g_dinv[i] = 1.0f; g_cnt[i] = 0; }   // deg starts at 1 (self loop)
}

__global__ void deg_kernel(const void* __restrict__ ei, const float* __restrict__ ew) {
    int e = blockIdx.x * blockDim.x + threadIdx.x;
    if (e < EE) {
        int d = edge_at(ei, (long long)EE + e);
        atomicAdd(&g_dinv[d], ew[e]);
        atomicAdd(&g_cnt[d], 1);
    }
}

// ---------------- scan: g_cnt -> exclusive rowptr ----------------
__global__ void scan1_kernel() {
    __shared__ int s[SCAN_B];
    int t = threadIdx.x;
    int i = blockIdx.x * SCAN_B + t;
    int v = (i < NN) ? g_cnt[i] : 0;
    s[t] = v;
    __syncthreads();
    for (int off = 1; off < SCAN_B; off <<= 1) {
        int tmp = (t >= off) ? s[t - off] : 0;
        __syncthreads();
        s[t] += tmp;
        __syncthreads();
    }
    if (i < NN) g_rowptr[i] = s[t] - v;
    if (t == SCAN_B - 1) g_blocksum[blockIdx.x] = s[t];
}

// scan3: each 256-thread block lies in exactly one scan1 region -> warp 0 computes
// the blocksum prefix inline (no separate scan2 kernel). Also folds rsqrt.
__global__ void scan3_kernel() {
    __shared__ int s_off;
    int blk = blockIdx.x;
    int b = (blk * 256) / SCAN_B;     // uniform within the block
    if (threadIdx.x < 32) {
        int sum = 0;
        for (int t = threadIdx.x; t < b; t += 32) sum += g_blocksum[t];
        #pragma unroll
        for (int o = 16; o > 0; o >>= 1) sum += __shfl_down_sync(0xffffffffu, sum, o);
        if (threadIdx.x == 0) s_off = sum;
    }
    __syncthreads();
    int i = blk * 256 + threadIdx.x;
    if (i < NN) {
        int v = g_rowptr[i] + s_off;
        g_rowptr[i] = v;
        g_cnt[i] = v;                          // write cursor
        g_dinv[i] = rsqrtf(g_dinv[i]);         // deg >= 1 always
    }
    if (i == 0) g_rowptr[NN] = EE;
}

// ---------------- CSR build (edges bucketed by dst) ----------------
__global__ void csr_kernel(const void* __restrict__ ei, const float* __restrict__ ew) {
    int e = blockIdx.x * blockDim.x + threadIdx.x;
    if (e < EE) {
        int s = edge_at(ei, e);
        int d = edge_at(ei, (long long)EE + e);
        float nrm = g_dinv[s] * ew[e] * g_dinv[d];
        int pos = atomicAdd(&g_cnt[d], 1);
        g_csr_src[pos] = s;
        g_csr_nrm[pos] = nrm;
    }
}

// ---------------- tensor-core GEMM (mma.sync HMMA) ----------------
// Y[n,128] = X[n,128] @ W[128,128] (+bias).
// W always dual-fp16 split (Whi+Wlo). X: fp32 input -> dual split (3 MMA terms);
// fp16 input -> used exactly (2 MMA terms).
#define BM 128
#define LDA 136                           // 128 + 8 pad halfs
#define TILE_BYTES (128 * LDA * 2)        // 34816
#define OFF_BHI 0
#define OFF_BLO (TILE_BYTES)
#define OFF_AHI (2 * TILE_BYTES)
#define OFF_ALO (3 * TILE_BYTES)
#define S_GEMM  (4 * TILE_BYTES)          // 139264 B dynamic smem (max case)

__device__ __forceinline__ uint32_t smem_u32(const void* p) {
    uint32_t a;
    asm("{ .reg .u64 t; cvta.to.shared.u64 t, %1; cvt.u32.u64 %0, t; }" : "=r"(a) : "l"(p));
    return a;
}

#define LDSM4(R, addr) \
    asm volatile("ldmatrix.sync.aligned.m8n8.x4.shared.b16 {%0,%1,%2,%3}, [%4];" \
        : "=r"((R)[0]), "=r"((R)[1]), "=r"((R)[2]), "=r"((R)[3]) : "r"(addr))

#define MMA16816(D, A, B0, B1) \
    asm volatile("mma.sync.aligned.m16n8k16.row.col.f32.f16.f16.f32 " \
        "{%0,%1,%2,%3}, {%4,%5,%6,%7}, {%8,%9}, {%0,%1,%2,%3};" \
        : "+f"((D)[0]), "+f"((D)[1]), "+f"((D)[2]), "+f"((D)[3]) \
        : "r"((A)[0]), "r"((A)[1]), "r"((A)[2]), "r"((A)[3]), "r"(B0), "r"(B1))

__device__ __forceinline__ void split2(float x, __half& hi, __half& lo) {
    hi = __float2half_rn(x);
    lo = __float2half_rn(x - __half2float(hi));
}

template <typename InT, typename OutT>
__global__ __launch_bounds__(256) void gemm_mma_kernel(const InT* __restrict__ X,
                                                       const float* __restrict__ W,
                                                       const float* __restrict__ bias,
                                                       OutT* __restrict__ Y, int n) {
    constexpr bool IN_HALF = (sizeof(InT) == 2);
    extern __shared__ char smem[];
    uint32_t sb = smem_u32(smem);
    int tid = threadIdx.x;
    int lane = tid & 31;
    int wid = tid >> 5;
    int row0 = blockIdx.x * BM;

    __half* Bhi = (__half*)(smem + OFF_BHI);
    __half* Blo = (__half*)(smem + OFF_BLO);
    __half* Ahi = (__half*)(smem + OFF_AHI);
    __half* Alo = (__half*)(smem + OFF_ALO);

    // ---- stage A ----
    if (IN_HALF) {
        // direct fp16 copy: 2048 chunks of 8 halfs (16B)
        const __half* Xh = (const __half*)X;
        #pragma unroll
        for (int j = 0; j < 8; j++) {
            int i8 = tid + 256 * j;
            int row = i8 >> 4;
            int c8 = (i8 & 15) << 3;
            uint4 v = make_uint4(0u, 0u, 0u, 0u);
            if (row0 + row < n)
                v = *(const uint4*)&Xh[(size_t)(row0 + row) * 128 + c8];
            *(uint4*)&Ahi[row * LDA + c8] = v;
        }
    } else {
        const float* Xf = (const float*)X;
        #pragma unroll
        for (int j = 0; j < 8; j++) {
            int i8 = tid + 256 * j;               // 2048 chunks of 8 floats
            int row = i8 >> 4;
            int c8 = (i8 & 15) << 3;
            float v[8];
            if (row0 + row < n) {
                *(float4*)&v[0] = *(const float4*)&Xf[(size_t)(row0 + row) * 128 + c8];
                *(float4*)&v[4] = *(const float4*)&Xf[(size_t)(row0 + row) * 128 + c8 + 4];
            } else {
                #pragma unroll
                for (int q = 0; q < 8; q++) v[q] = 0.f;
            }
            __half h[8], l[8];
            #pragma unroll
            for (int q = 0; q < 8; q++) split2(v[q], h[q], l[q]);
            *(uint4*)&Ahi[row * LDA + c8] = *(uint4*)h;
            *(uint4*)&Alo[row * LDA + c8] = *(uint4*)l;
        }
    }
    // ---- stage B = W^T (hi/lo): thread owns 8 consecutive k for one n ----
    #pragma unroll
    for (int j = 0; j < 8; j++) {
        int i8 = tid + 256 * j;                   // 0..2047
        int ncol = i8 & 127;
        int k0 = (i8 >> 7) << 3;
        __half h[8], l[8];
        #pragma unroll
        for (int q = 0; q < 8; q++) {
            float v = __ldg(&W[(size_t)(k0 + q) * 128 + ncol]);   // coalesced across warp
            split2(v, h[q], l[q]);
        }
        *(uint4*)&Bhi[ncol * LDA + k0] = *(uint4*)h;
        *(uint4*)&Blo[ncol * LDA + k0] = *(uint4*)l;
    }
    __syncthreads();

    // ---- warp tiling: 8 warps = 4(M) x 2(N); warp tile 32x64 ----
    int wm = wid & 3;
    int wn = wid >> 2;
    int m_base = wm * 32, n_base = wn * 64;

    float d[2][8][4];
    #pragma unroll
    for (int mt = 0; mt < 2; mt++)
        #pragma unroll
        for (int nt = 0; nt < 8; nt++)
            #pragma unroll
            for (int q = 0; q < 4; q++) d[mt][nt][q] = 0.f;

    int aRow = lane & 15, aK = (lane >> 4) << 3;
    int bRow = (lane & 7) + ((lane >> 4) << 3), bK = ((lane >> 3) & 1) << 3;

    uint32_t sAhi = sb + OFF_AHI, sAlo = sb + OFF_ALO;
    uint32_t sBhi = sb + OFF_BHI, sBlo = sb + OFF_BLO;

    #pragma unroll
    for (int ks = 0; ks < 8; ks++) {
        int k0 = ks * 16;
        uint32_t ah[2][4], al[2][4];
        #pragma unroll
        for (int mt = 0; mt < 2; mt++) {
            uint32_t off = (uint32_t)((m_base + mt * 16 + aRow) * LDA + k0 + aK) * 2;
            LDSM4(ah[mt], sAhi + off);
            if (!IN_HALF) LDSM4(al[mt], sAlo + off);
        }
        uint32_t bh[4][4], bl[4][4];
        #pragma unroll
        for (int bt = 0; bt < 4; bt++) {
            uint32_t off = (uint32_t)((n_base + bt * 16 + bRow) * LDA + k0 + bK) * 2;
            LDSM4(bh[bt], sBhi + off);
            LDSM4(bl[bt], sBlo + off);
        }
        #pragma unroll
        for (int mt = 0; mt < 2; mt++)
            #pragma unroll
            for (int bt = 0; bt < 4; bt++)
                #pragma unroll
                for (int h = 0; h < 2; h++) {
                    int nt = bt * 2 + h;
                    MMA16816(d[mt][nt], ah[mt], bh[bt][2 * h], bh[bt][2 * h + 1]);       // X(hi)*Whi
                    MMA16816(d[mt][nt], ah[mt], bl[bt][2 * h], bl[bt][2 * h + 1]);       // X(hi)*Wlo
                    if (!IN_HALF)
                        MMA16816(d[mt][nt], al[mt], bh[bt][2 * h], bh[bt][2 * h + 1]);   // Xlo*Whi
                }
    }

    // ---- epilogue ----
    #pragma unroll
    for (int mt = 0; mt < 2; mt++) {
        int rlo = row0 + m_base + mt * 16 + (lane >> 2);
        int rhi = rlo + 8;
        #pragma unroll
        for (int nt = 0; nt < 8; nt++) {
            int c = n_base + nt * 8 + (lane & 3) * 2;
            float b0 = bias ? __ldg(&bias[c]) : 0.f;
            float b1 = bias ? __ldg(&bias[c + 1]) : 0.f;
            float v0 = d[mt][nt][0] + b0, v1 = d[mt][nt][1] + b1;
            float v2 = d[mt][nt][2] + b0, v3 = d[mt][nt][3] + b1;
            if (sizeof(OutT) == 2) {
                if (rlo < n) *(__half2*)&((__half*)Y)[(size_t)rlo * 128 + c] = __floats2half2_rn(v0, v1);
                if (rhi < n) *(__half2*)&((__half*)Y)[(size_t)rhi * 128 + c] = __floats2half2_rn(v2, v3);
            } else {
                if (rlo < n) *(float2*)&((float*)Y)[(size_t)rlo * 128 + c] = make_float2(v0, v1);
                if (rhi < n) *(float2*)&((float*)Y)[(size_t)rhi * 128 + c] = make_float2(v2, v3);
            }
        }
    }
}

// ---------------- aggregate: Y[i] = relu(sum_e nrm*H[src] + dinv_i^2*H[i] + b) ----------------
// H fp16 gather, fp32 accumulate, fp16 output (feeds fp16-input GEMM).
__device__ __forceinline__ void acc_edge(float4& acc, float nv, uint2 v) {
    __half2* ph = (__half2*)&v;
    float2 f01 = __half22float2(ph[0]);
    float2 f23 = __half22float2(ph[1]);
    acc.x = fmaf(nv, f01.x, acc.x);
    acc.y = fmaf(nv, f01.y, acc.y);
    acc.z = fmaf(nv, f23.x, acc.z);
    acc.w = fmaf(nv, f23.y, acc.w);
}

__global__ void aggregate_kernel(const __half* __restrict__ H, const float* __restrict__ bias,
                                 __half* __restrict__ Y) {
    int warp = (blockIdx.x * blockDim.x + threadIdx.x) >> 5;
    int lane = threadIdx.x & 31;
    if (warp >= NN) return;
    int beg = g_rowptr[warp];
    int end = g_rowptr[warp + 1];
    const uint2* __restrict__ H2 = (const uint2*)H;

    float4 acc = make_float4(0.f, 0.f, 0.f, 0.f);
    int e = beg;
    for (; e + 4 <= end; e += 4) {
        int   s0 = g_csr_src[e + 0], s1 = g_csr_src[e + 1];
        int   s2 = g_csr_src[e + 2], s3 = g_csr_src[e + 3];
        float n0 = g_csr_nrm[e + 0], n1 = g_csr_nrm[e + 1];
        float n2 = g_csr_nrm[e + 2], n3 = g_csr_nrm[e + 3];
        uint2 v0 = __ldg(H2 + (size_t)s0 * 32 + lane);
        uint2 v1 = __ldg(H2 + (size_t)s1 * 32 + lane);
        uint2 v2 = __ldg(H2 + (size_t)s2 * 32 + lane);
        uint2 v3 = __ldg(H2 + (size_t)s3 * 32 + lane);
        acc_edge(acc, n0, v0);
        acc_edge(acc, n1, v1);
        acc_edge(acc, n2, v2);
        acc_edge(acc, n3, v3);
    }
    for (; e < end; e++) {
        int s = g_csr_src[e];
        float nv = g_csr_nrm[e];
        uint2 v = __ldg(H2 + (size_t)s * 32 + lane);
        acc_edge(acc, nv, v);
    }
    float di = g_dinv[warp];
    float sn = di * di;
    uint2 vs = __ldg(H2 + (size_t)warp * 32 + lane);
    acc_edge(acc, sn, vs);

    float4 b = __ldg((const float4*)bias + lane);
    float r0 = fmaxf(acc.x + b.x, 0.f);
    float r1 = fmaxf(acc.y + b.y, 0.f);
    float r2 = fmaxf(acc.z + b.z, 0.f);
    float r3 = fmaxf(acc.w + b.w, 0.f);
    uint2 outv;
    *(__half2*)&outv.x = __floats2half2_rn(r0, r1);
    *(__half2*)&outv.y = __floats2half2_rn(r2, r3);
    ((uint2*)Y)[(size_t)warp * 32 + lane] = outv;
}

// ---------------- launch ----------------
extern "C" void kernel_launch(void* const* d_in, const int* in_sizes, int n_in,
                              void* d_out, int out_size) {
    const float* x = nullptr;
    const float* ew = nullptr;
    const void*  ei = nullptr;
    const float* Ws[3] = {nullptr, nullptr, nullptr};
    const float* bs[3] = {nullptr, nullptr, nullptr};
    int nW = 0, nb = 0;
    for (int i = 0; i < n_in; i++) {
        long long sz = in_sizes[i];
        if      (sz == (long long)NN * FD)  x  = (const float*)d_in[i];
        else if (sz == EE)                  ew = (const float*)d_in[i];
        else if (sz == 2LL * EE)            ei = d_in[i];
        else if (sz == FD * FD) { if (nW < 3) Ws[nW++] = (const float*)d_in[i]; }
        else if (sz == FD)      { if (nb < 3) bs[nb++] = (const float*)d_in[i]; }
    }
    const float *W1 = Ws[0], *W2 = Ws[1], *Wfc = Ws[2];
    const float *b1 = bs[0], *b2 = bs[1], *bfc = bs[2];
    float* out = (float*)d_out;

    __half* hA; cudaGetSymbolAddress((void**)&hA, g_hA16);
    __half* hB; cudaGetSymbolAddress((void**)&hB, g_hB16);

    static cudaStream_t s2 = nullptr;
    static cudaEvent_t evFork = nullptr, evJoin = nullptr;
    if (!s2) {
        cudaStreamCreateWithFlags(&s2, cudaStreamNonBlocking);
        cudaEventCreateWithFlags(&evFork, cudaEventDisableTiming);
        cudaEventCreateWithFlags(&evJoin, cudaEventDisableTiming);
        cudaFuncSetAttribute((const void*)gemm_mma_kernel<float, __half>,
                             cudaFuncAttributeMaxDynamicSharedMemorySize, S_GEMM);
        cudaFuncSetAttribute((const void*)gemm_mma_kernel<__half, __half>,
                             cudaFuncAttributeMaxDynamicSharedMemorySize, S_GEMM);
        cudaFuncSetAttribute((const void*)gemm_mma_kernel<__half, float>,
                             cudaFuncAttributeMaxDynamicSharedMemorySize, S_GEMM);
    }

    int nodeBlocks = (NN + 255) / 256;
    int edgeBlocks = (EE + 255) / 256;
    int gemmBlocks = (NN + BM - 1) / BM;
    int aggBlocks  = (NN + 7) / 8;

    cudaEventRecord(evFork, 0);
    cudaStreamWaitEvent(s2, evFork, 0);

    init_kernel<<<nodeBlocks, 256, 0, s2>>>((const unsigned int*)ei);
    deg_kernel<<<edgeBlocks, 256, 0, s2>>>(ei, ew);
    scan1_kernel<<<SCAN_NB, SCAN_B, 0, s2>>>();
    scan3_kernel<<<nodeBlocks, 256, 0, s2>>>();
    csr_kernel<<<edgeBlocks, 256, 0, s2>>>(ei, ew);
    cudaEventRecord(evJoin, s2);

    // GEMM1 overlaps prep (fp32 input -> dual split). Output fp16.
    gemm_mma_kernel<float, __half><<<gemmBlocks, 256, S_GEMM>>>(x, W1, nullptr, hA, NN);

    cudaStreamWaitEvent(0, evJoin, 0);

    aggregate_kernel<<<aggBlocks, 256>>>(hA, b1, hB);
    gemm_mma_kernel<__half, __half><<<gemmBlocks, 256, S_GEMM>>>(hB, W2, nullptr, hA, NN);
    aggregate_kernel<<<aggBlocks, 256>>>(hA, b2, hB);
    gemm_mma_kernel<__half, float><<<gemmBlocks, 256, S_GEMM>>>(hB, Wfc, bfc, out, NN);
}